// round 9
// baseline (speedup 1.0000x reference)
#include <cuda_runtime.h>
#include <cuda_bf16.h>

// B=2, L=256, D=256. Single fused kernel, 128 blocks x 512 threads.
//   phase 1: GEMM raw[l, n] for 8 n-cols (n0=8*dg) via f32x2 FMA.
//            X tile staged DUPLICATED (x,x) in smem -> LDS.64 feeds FMA2 directly.
//            Register double-buffer: LDG next tile during compute.
//   phase 2: epilogue a = (re,im) * rsqrt(m2) * exp(-m2) -> smem
//   phase 3: reverse complex scans, 2 per 256-thread group.

__device__ __forceinline__ float2 cmul(float2 a, float2 b) {
    return make_float2(a.x * b.x - a.y * b.y, a.x * b.y + a.y * b.x);
}
__device__ __forceinline__ float2 cadd(float2 a, float2 b) {
    return make_float2(a.x + b.x, a.y + b.y);
}

// Shared (bytes), phase-aliased:
//  phase 1: [0, 32896)  Xs2[16][257] float2 (duplicated x, pad 257)
//           [32896, 41088) shW[256][8] float
//  phase 2/3: [0,8192) sA[4][256] float2 ; [8192,12288) xsr[4][256] float
//             [12288..13056) wagA/wagY/preY [4][8] float2
#define SMEM_BYTES 41088

__global__ __launch_bounds__(512)
void sioconv_fused(const float* __restrict__ X, const float* __restrict__ W,
                   const float* __restrict__ h0r, const float* __restrict__ h0i,
                   float* __restrict__ out) {
    __shared__ __align__(16) char smem[SMEM_BYTES];

    const int b  = blockIdx.x >> 6;
    const int dg = blockIdx.x & 63;
    const int n0 = dg * 8;
    const int t  = threadIdx.x;       // 0..511
    const int lt = t & 255;           // l row this thread accumulates
    const int ng = t >> 8;            // 0/1: which 4 n-columns (2 pairs)

    float2* Xs2 = (float2*)smem;            // [16][257]
    float*  shW = (float*)(smem + 32896);   // [256][8]

    const float* Xb = X + b * 256 * 256;

    // ---- W staging: shW[k][n] = W[n0+n][k], 2048 elems / 512 thr = 4 each
#pragma unroll
    for (int i = 0; i < 4; i++) {
        int e = t + 512 * i;
        int n = e >> 8;
        int k = e & 255;
        shW[k * 8 + n] = W[(n0 + n) * 256 + k];
    }

    // ---- staging index for X tiles: thread owns row sl, cols sc..sc+7
    const int sl = t >> 1;
    const int sc = (t & 1) * 8;

    unsigned long long acc[2] = {0ull, 0ull};

    // prologue: load tile 0
    float4 v0 = *(const float4*)(Xb + sl * 256 + 0 + sc);
    float4 v1 = *(const float4*)(Xb + sl * 256 + 0 + sc + 4);
    {
        float vv[8] = {v0.x, v0.y, v0.z, v0.w, v1.x, v1.y, v1.z, v1.w};
#pragma unroll
        for (int q = 0; q < 8; q++)
            Xs2[(sc + q) * 257 + sl] = make_float2(vv[q], vv[q]);
    }
    __syncthreads();

#pragma unroll 1
    for (int tile = 0; tile < 16; tile++) {
        const int k0 = tile * 16;
        // prefetch next tile into registers (overlaps with compute below)
        if (tile < 15) {
            v0 = *(const float4*)(Xb + sl * 256 + k0 + 16 + sc);
            v1 = *(const float4*)(Xb + sl * 256 + k0 + 16 + sc + 4);
        }

        const unsigned long long* xrow =
            (const unsigned long long*)(Xs2) + lt;   // stride 257 per kk
        const float* wbase = shW + k0 * 8 + ng * 4;
#pragma unroll
        for (int kk = 0; kk < 16; kk++) {
            unsigned long long x2 = xrow[kk * 257];
            ulonglong2 wpair = *(const ulonglong2*)(wbase + kk * 8);
            asm("fma.rn.f32x2 %0, %1, %2, %0;" : "+l"(acc[0]) : "l"(x2), "l"(wpair.x));
            asm("fma.rn.f32x2 %0, %1, %2, %0;" : "+l"(acc[1]) : "l"(x2), "l"(wpair.y));
        }
        __syncthreads();   // reads of this tile done
        if (tile < 15) {
            float vv[8] = {v0.x, v0.y, v0.z, v0.w, v1.x, v1.y, v1.z, v1.w};
#pragma unroll
            for (int q = 0; q < 8; q++)
                Xs2[(sc + q) * 257 + sl] = make_float2(vv[q], vv[q]);
            __syncthreads();   // writes visible
        }
    }
    __syncthreads();   // safe to alias smem

    float2* sA   = (float2*)smem;            // [4][256]
    float*  xsr  = (float*)(smem + 8192);    // [4][256]
    float2* wagA = (float2*)(smem + 12288);  // [4][8]
    float2* wagY = (float2*)(smem + 12544);  // [4][8]
    float2* preY = (float2*)(smem + 12800);  // [4][8]

    // ---- epilogue: thread (lt, ng) owns d-indices j = ng*2 + p
#pragma unroll
    for (int p = 0; p < 2; p++) {
        float re, im;
        asm("mov.b64 {%0, %1}, %2;" : "=f"(re), "=f"(im) : "l"(acc[p]));
        float mag2 = re * re + im * im;
        float s = rsqrtf(mag2) * expf(-mag2);
        int j = ng * 2 + p;
        sA[j * 256 + lt] = make_float2(re * s, im * s);
    }

    // ---- stage xhat real parts: xsr[j][l], 1024 elems / 512 thr = 2 each
#pragma unroll
    for (int i = 0; i < 2; i++) {
        int e = t + 512 * i;
        int l = e >> 2;
        int j = e & 3;
        int d = dg * 4 + j;
        xsr[j * 256 + l] = (l == 0) ? h0r[d] : Xb[(l - 1) * 256 + d];
    }
    __syncthreads();

    // ---- scan: group g = t>>8 handles j = 2g, 2g+1
    const int g = t >> 8;
    const int tl = t & 255;        // reversed index within group
    const int l = 255 - tl;
    const int lane = t & 31;
    const int w = tl >> 5;         // 0..7

    float2 A[2], Y[2];
#pragma unroll
    for (int p = 0; p < 2; p++) {
        int j = 2 * g + p;
        float2 a = sA[j * 256 + l];
        float2 xh;
        xh.x = xsr[j * 256 + l];
        xh.y = (l == 0) ? h0i[dg * 4 + j] : 0.f;
        A[p] = a;
        Y[p] = cmul(a, xh);
    }

    const unsigned mask = 0xffffffffu;
#pragma unroll
    for (int o = 1; o < 32; o <<= 1) {
#pragma unroll
        for (int p = 0; p < 2; p++) {
            float2 pA, pY;
            pA.x = __shfl_up_sync(mask, A[p].x, o);
            pA.y = __shfl_up_sync(mask, A[p].y, o);
            pY.x = __shfl_up_sync(mask, Y[p].x, o);
            pY.y = __shfl_up_sync(mask, Y[p].y, o);
            if (lane >= o) {
                float2 nY = cadd(Y[p], cmul(A[p], pY));
                float2 nA = cmul(A[p], pA);
                Y[p] = nY;
                A[p] = nA;
            }
        }
    }

    if (lane == 31) {
#pragma unroll
        for (int p = 0; p < 2; p++) {
            int j = 2 * g + p;
            wagA[j * 8 + w] = A[p];
            wagY[j * 8 + w] = Y[p];
        }
    }
    __syncthreads();
    if (tl < 2) {
        int j = 2 * g + tl;
        float2 pY = make_float2(0.f, 0.f);
#pragma unroll
        for (int w2 = 0; w2 < 8; w2++) {
            preY[j * 8 + w2] = pY;
            pY = cadd(wagY[j * 8 + w2], cmul(wagA[j * 8 + w2], pY));
        }
    }
    __syncthreads();

    float res[2];
#pragma unroll
    for (int p = 0; p < 2; p++) {
        int j = 2 * g + p;
        float2 Yf = Y[p];
        if (w > 0) Yf = cadd(Yf, cmul(A[p], preY[j * 8 + w]));
        float r = Yf.x;
        if (l >= 1)   r += xsr[j * 256 + (l - 1)];
        if (l == 255) r += Xb[255 * 256 + dg * 4 + j];
        res[p] = r;
    }
    *(float2*)(out + (b * 256 + l) * 256 + dg * 4 + 2 * g) =
        make_float2(res[0], res[1]);
}

extern "C" void kernel_launch(void* const* d_in, const int* in_sizes, int n_in,
                              void* d_out, int out_size) {
    const float* x   = (const float*)d_in[0];
    const float* W   = (const float*)d_in[1];
    const float* h0r = (const float*)d_in[2];
    const float* h0i = (const float*)d_in[3];
    float* out = (float*)d_out;

    sioconv_fused<<<128, 512>>>(x, W, h0r, h0i, out);
}

// round 10
// speedup vs baseline: 1.3795x; 1.3795x over previous
#include <cuda_runtime.h>
#include <cuda_bf16.h>

// B=2, L=256, D=256. One fused kernel, 128 blocks x 512 threads.
// Dynamic smem: Xs[256][130] floats (133120 B) + shWk[128][8] float2 (8192 B).
#define XS_BYTES  133120
#define SMEM_DYN  (XS_BYTES + 8192)

__device__ __forceinline__ float2 cmul(float2 a, float2 b) {
    return make_float2(a.x * b.x - a.y * b.y, a.x * b.y + a.y * b.x);
}
__device__ __forceinline__ float2 cadd(float2 a, float2 b) {
    return make_float2(a.x + b.x, a.y + b.y);
}
#define FMA2(acc, x, w) \
    asm("fma.rn.f32x2 %0, %1, %2, %0;" : "+l"(acc) : "l"(x), "l"(w))
#define ADD2(acc, y) \
    asm("add.rn.f32x2 %0, %0, %1;" : "+l"(acc) : "l"(y))

__global__ __launch_bounds__(512, 1)
void sioconv_fused(const float* __restrict__ X, const float* __restrict__ W,
                   const float* __restrict__ h0r, const float* __restrict__ h0i,
                   float* __restrict__ out) {
    extern __shared__ __align__(16) char smem[];
    float*  Xs   = (float*)smem;                 // [256][130], tile of 128 k
    float2* shWk = (float2*)(smem + XS_BYTES);   // [128 k2][8 n] (W[n][2k],W[n][2k+1])

    const int b  = blockIdx.x >> 6;
    const int dg = blockIdx.x & 63;
    const int n0 = dg * 8;
    const int t  = threadIdx.x;      // 0..511
    const int lt = t & 255;          // l row
    const int kh = t >> 8;           // k-half within each tile

    const float* Xb = X + b * 65536;

    // ---- stage W (k-pair-major): 1024 float2 entries, 2 per thread
#pragma unroll
    for (int i = 0; i < 2; i++) {
        int e = t + 512 * i;
        int n = e >> 7, k2 = e & 127;
        shWk[k2 * 8 + n] = *(const float2*)(W + (n0 + n) * 256 + 2 * k2);
    }

    // ---- stage X tile 0 (k 0..127): contiguous LDG.128 / STS.64
    float4 v[16];
#pragma unroll
    for (int i = 0; i < 16; i++) {
        int idx = t + 512 * i;
        int l = idx >> 5, c4 = idx & 31;
        v[i] = *(const float4*)(Xb + l * 256 + 4 * c4);
    }
#pragma unroll
    for (int i = 0; i < 16; i++) {
        int idx = t + 512 * i;
        int l = idx >> 5, c4 = idx & 31;
        float* p = Xs + l * 130 + 4 * c4;
        *(float2*)(p)     = make_float2(v[i].x, v[i].y);
        *(float2*)(p + 2) = make_float2(v[i].z, v[i].w);
    }
    __syncthreads();

    // ---- prefetch tile 1 into registers (overlaps tile-0 compute)
#pragma unroll
    for (int i = 0; i < 16; i++) {
        int idx = t + 512 * i;
        int l = idx >> 5, c4 = idx & 31;
        v[i] = *(const float4*)(Xb + l * 256 + 128 + 4 * c4);
    }

    // acc[n] = (sum over even k, sum over odd k) for n = n0..n0+7
    unsigned long long acc[8] = {0ull,0ull,0ull,0ull,0ull,0ull,0ull,0ull};

    // ---- compute tile 0: this thread's k2 range = kh*32 .. kh*32+31
    {
        const float*  xr = Xs + lt * 130 + kh * 64;
        const float2* wr = shWk + (kh * 32) * 8;
#pragma unroll
        for (int j = 0; j < 32; j++) {
            unsigned long long x2 = *(const unsigned long long*)(xr + 2 * j);
            const ulonglong2* wp = (const ulonglong2*)(wr + j * 8);
            ulonglong2 w01 = wp[0], w23 = wp[1], w45 = wp[2], w67 = wp[3];
            unsigned long long wv[8];
            wv[0] = w01.x; wv[1] = w01.y; wv[2] = w23.x; wv[3] = w23.y;
            wv[4] = w45.x; wv[5] = w45.y; wv[6] = w67.x; wv[7] = w67.y;
#pragma unroll
            for (int n = 0; n < 8; n++) FMA2(acc[n], x2, wv[n]);
        }
    }
    __syncthreads();   // tile-0 reads done

    // ---- store tile 1
#pragma unroll
    for (int i = 0; i < 16; i++) {
        int idx = t + 512 * i;
        int l = idx >> 5, c4 = idx & 31;
        float* p = Xs + l * 130 + 4 * c4;
        *(float2*)(p)     = make_float2(v[i].x, v[i].y);
        *(float2*)(p + 2) = make_float2(v[i].z, v[i].w);
    }
    __syncthreads();

    // ---- compute tile 1: global k2 = 64 + kh*32 + j
    {
        const float*  xr = Xs + lt * 130 + kh * 64;
        const float2* wr = shWk + (64 + kh * 32) * 8;
#pragma unroll
        for (int j = 0; j < 32; j++) {
            unsigned long long x2 = *(const unsigned long long*)(xr + 2 * j);
            const ulonglong2* wp = (const ulonglong2*)(wr + j * 8);
            ulonglong2 w01 = wp[0], w23 = wp[1], w45 = wp[2], w67 = wp[3];
            unsigned long long wv[8];
            wv[0] = w01.x; wv[1] = w01.y; wv[2] = w23.x; wv[3] = w23.y;
            wv[4] = w45.x; wv[5] = w45.y; wv[6] = w67.x; wv[7] = w67.y;
#pragma unroll
            for (int n = 0; n < 8; n++) FMA2(acc[n], x2, wv[n]);
        }
    }
    __syncthreads();   // all Xs reads done; smem can be aliased

    // ---- phase-2 smem layout (aliases Xs region)
    unsigned long long* scratch = (unsigned long long*)smem;   // [256][8]
    float2* sA   = (float2*)(smem + 16384);   // [4][256]
    float*  xsr  = (float*)(smem + 24576);    // [4][256]
    float2* wagA = (float2*)(smem + 28672);   // [4][8]
    float2* wagY = (float2*)(smem + 28928);   // [4][8]
    float2* preY = (float2*)(smem + 29184);   // [4][8]

    // ---- combine k-halves
    if (kh == 1) {
#pragma unroll
        for (int n = 0; n < 8; n++) scratch[lt * 8 + n] = acc[n];
    }
    __syncthreads();
    if (kh == 0) {
#pragma unroll
        for (int p = 0; p < 4; p++) {
            unsigned long long aRe = acc[2 * p], aIm = acc[2 * p + 1];
            ADD2(aRe, scratch[lt * 8 + 2 * p]);
            ADD2(aIm, scratch[lt * 8 + 2 * p + 1]);
            float r0, r1, i0, i1;
            asm("mov.b64 {%0, %1}, %2;" : "=f"(r0), "=f"(r1) : "l"(aRe));
            asm("mov.b64 {%0, %1}, %2;" : "=f"(i0), "=f"(i1) : "l"(aIm));
            float re = r0 + r1;
            float im = i0 + i1;
            float mag2 = re * re + im * im;
            float s = rsqrtf(mag2) * expf(-mag2);
            sA[p * 256 + lt] = make_float2(re * s, im * s);
        }
    }
    // ---- stage xhat real parts: xsr[j][l]
#pragma unroll
    for (int i = 0; i < 2; i++) {
        int e = t + 512 * i;
        int l = e >> 2;
        int j = e & 3;
        int d = dg * 4 + j;
        xsr[j * 256 + l] = (l == 0) ? h0r[d] : Xb[(l - 1) * 256 + d];
    }
    __syncthreads();

    // ---- reverse complex scan: group g = t>>8 handles j = 2g, 2g+1
    const int g = t >> 8;
    const int tl = t & 255;       // reversed index
    const int l = 255 - tl;
    const int lane = t & 31;
    const int w = tl >> 5;

    float2 A[2], Y[2];
#pragma unroll
    for (int p = 0; p < 2; p++) {
        int j = 2 * g + p;
        float2 a = sA[j * 256 + l];
        float2 xh;
        xh.x = xsr[j * 256 + l];
        xh.y = (l == 0) ? h0i[dg * 4 + j] : 0.f;
        A[p] = a;
        Y[p] = cmul(a, xh);
    }

    const unsigned mask = 0xffffffffu;
#pragma unroll
    for (int o = 1; o < 32; o <<= 1) {
#pragma unroll
        for (int p = 0; p < 2; p++) {
            float2 pA, pY;
            pA.x = __shfl_up_sync(mask, A[p].x, o);
            pA.y = __shfl_up_sync(mask, A[p].y, o);
            pY.x = __shfl_up_sync(mask, Y[p].x, o);
            pY.y = __shfl_up_sync(mask, Y[p].y, o);
            if (lane >= o) {
                float2 nY = cadd(Y[p], cmul(A[p], pY));
                float2 nA = cmul(A[p], pA);
                Y[p] = nY;
                A[p] = nA;
            }
        }
    }

    if (lane == 31) {
#pragma unroll
        for (int p = 0; p < 2; p++) {
            int j = 2 * g + p;
            wagA[j * 8 + w] = A[p];
            wagY[j * 8 + w] = Y[p];
        }
    }
    __syncthreads();
    if (tl < 2) {
        int j = 2 * g + tl;
        float2 pY = make_float2(0.f, 0.f);
#pragma unroll
        for (int w2 = 0; w2 < 8; w2++) {
            preY[j * 8 + w2] = pY;
            pY = cadd(wagY[j * 8 + w2], cmul(wagA[j * 8 + w2], pY));
        }
    }
    __syncthreads();

    float res[2];
#pragma unroll
    for (int p = 0; p < 2; p++) {
        int j = 2 * g + p;
        float2 Yf = Y[p];
        if (w > 0) Yf = cadd(Yf, cmul(A[p], preY[j * 8 + w]));
        float r = Yf.x;
        if (l >= 1)   r += xsr[j * 256 + (l - 1)];
        if (l == 255) r += Xb[255 * 256 + dg * 4 + j];
        res[p] = r;
    }
    *(float2*)(out + (b * 256 + l) * 256 + dg * 4 + 2 * g) =
        make_float2(res[0], res[1]);
}

extern "C" void kernel_launch(void* const* d_in, const int* in_sizes, int n_in,
                              void* d_out, int out_size) {
    const float* x   = (const float*)d_in[0];
    const float* W   = (const float*)d_in[1];
    const float* h0r = (const float*)d_in[2];
    const float* h0i = (const float*)d_in[3];
    float* out = (float*)d_out;

    cudaFuncSetAttribute(sioconv_fused,
                         cudaFuncAttributeMaxDynamicSharedMemorySize, SMEM_DYN);
    sioconv_fused<<<128, 512, SMEM_DYN>>>(x, W, h0r, h0i, out);
}